// round 13
// baseline (speedup 1.0000x reference)
#include <cuda_runtime.h>
#include <cuda_bf16.h>
#include <math.h>

// Problem constants (fixed by the dataset)
#define NN 500000
#define EE 8000000
#define IN_DIM 128
#define H1 32
#define H2 16
#define SCAN_BLK 1024
#define NB_SCAN ((NN + SCAN_BLK - 1) / SCAN_BLK)   // 489

// Scratch (device globals; no cudaMalloc allowed)
__device__ float g_A[NN * H1];        // y1 = (x@W1)*dinv
__device__ float g_C[NN * H2];        // y2 = (h1@W2)*dinv
__device__ int   g_eidx[EE];          // CSR: src ids grouped by dst
__device__ int   g_cnt[NN];           // edge in-degree (no self loop)
__device__ int   g_cur[NN];           // fill cursors (primed to rowstart)
__device__ int   g_scan[NN];          // per-block inclusive scan of cnt
__device__ int   g_bsum[NB_SCAN];     // block totals
__device__ int   g_boff[NB_SCAN];     // exclusive scan of block totals
__device__ int   g_rowstart[NN + 1];
__device__ float g_dinv[NN];

// ---------------- packed f32x2 helpers --------------------------------------

union F2U { unsigned long long u; float2 f; };

__device__ __forceinline__ unsigned long long pack_dup(float x) {
    unsigned long long r;
    asm("mov.b64 %0, {%1, %1};" : "=l"(r) : "f"(x));
    return r;
}
__device__ __forceinline__ void ffma2(unsigned long long& acc,
                                      unsigned long long a, unsigned long long b) {
    asm("fma.rn.f32x2 %0, %1, %2, %0;" : "+l"(acc) : "l"(a), "l"(b));
}

// ---------------- stream/event context (created once, pre-main) --------------

namespace {
struct Ctx {
    cudaStream_t s1 = 0;
    cudaEvent_t e1 = 0, e2 = 0;
    bool ok = false;
    Ctx() {
        ok = (cudaStreamCreateWithFlags(&s1, cudaStreamNonBlocking) == cudaSuccess) &&
             (cudaEventCreateWithFlags(&e1, cudaEventDisableTiming) == cudaSuccess) &&
             (cudaEventCreateWithFlags(&e2, cudaEventDisableTiming) == cudaSuccess);
    }
};
Ctx g_ctx;
}

// ---------------- init / histogram / CSR fill -------------------------------

__global__ void k_init(int n4) {   // n4 = NN/4, zero cnt only
    int i = blockIdx.x * blockDim.x + threadIdx.x;
    if (i < n4) ((int4*)g_cnt)[i] = make_int4(0, 0, 0, 0);
}

__global__ void k_hist(const int* __restrict__ ei, int e) {
    int i = blockIdx.x * blockDim.x + threadIdx.x;   // over e/4
    if (i >= (e >> 2)) return;
    int4 d = ((const int4*)(ei + e))[i];
    atomicAdd(&g_cnt[d.x], 1);
    atomicAdd(&g_cnt[d.y], 1);
    atomicAdd(&g_cnt[d.z], 1);
    atomicAdd(&g_cnt[d.w], 1);
}

// ---------------- two-level exclusive scan of g_cnt -> g_rowstart -----------

__global__ void k_scan_a(int n) {
    __shared__ int s[SCAN_BLK];
    int t = threadIdx.x;
    int i = blockIdx.x * SCAN_BLK + t;
    int v = (i < n) ? g_cnt[i] : 0;
    s[t] = v;
    __syncthreads();
    #pragma unroll
    for (int off = 1; off < SCAN_BLK; off <<= 1) {
        int tv = (t >= off) ? s[t - off] : 0;
        __syncthreads();
        s[t] += tv;
        __syncthreads();
    }
    if (i < n) g_scan[i] = s[t];
    if (t == SCAN_BLK - 1) g_bsum[blockIdx.x] = s[t];
}

__global__ void k_scan_b(int nb) {
    __shared__ int s[SCAN_BLK];
    int t = threadIdx.x;
    int v = (t < nb) ? g_bsum[t] : 0;
    s[t] = v;
    __syncthreads();
    #pragma unroll
    for (int off = 1; off < SCAN_BLK; off <<= 1) {
        int tv = (t >= off) ? s[t - off] : 0;
        __syncthreads();
        s[t] += tv;
        __syncthreads();
    }
    if (t < nb) g_boff[t] = s[t] - v;   // exclusive
}

// writes rowstart AND primes the fill cursors with it
__global__ void k_scan_c(int n, int e) {
    int i = blockIdx.x * blockDim.x + threadIdx.x;
    if (i < n) {
        int rs = g_scan[i] - g_cnt[i] + g_boff[i / SCAN_BLK];  // exclusive
        g_rowstart[i] = rs;
        g_cur[i] = rs;
    }
    if (i == 0) g_rowstart[n] = e;
}

// cursor-primed fill: atomicAdd's return IS the slot (no rowstart load)
__global__ void k_fill(const int* __restrict__ ei, int e) {
    int i = blockIdx.x * blockDim.x + threadIdx.x;   // over e/4
    if (i >= (e >> 2)) return;
    int4 s = ((const int4*)ei)[i];
    int4 d = ((const int4*)(ei + e))[i];
    int p0 = atomicAdd(&g_cur[d.x], 1);
    int p1 = atomicAdd(&g_cur[d.y], 1);
    int p2 = atomicAdd(&g_cur[d.z], 1);
    int p3 = atomicAdd(&g_cur[d.w], 1);
    g_eidx[p0] = s.x;
    g_eidx[p1] = s.y;
    g_eidx[p2] = s.z;
    g_eidx[p3] = s.w;
}

// ---------------- GEMM1: g_A = (x @ W1) * dinv[row]; also stores dinv -------
// Register-blocked 8x8: block = 128 threads covering 256 rows x 32 cols.
// Per warp-k: 8 wf (W) + 8 wf (x) for 32 FFMA2. Computes dinv inline
// (needs only g_cnt), so it can overlap the scan/fill chain.

__global__ void __launch_bounds__(128, 4)
k_gemm1(const float* __restrict__ x, const float* __restrict__ W1, int n) {
    __shared__ __align__(16) float ws[IN_DIM * H1];   // 16 KB
    __shared__ __align__(16) float xs[256 * 36];      // 36 KB
    const int t = threadIdx.x;
    const int row0 = blockIdx.x * 256;

    {   // W1: 128x32 = 1024 float4
        const float4* w4 = (const float4*)W1;
        float4* s4 = (float4*)ws;
        #pragma unroll
        for (int i = t; i < 1024; i += 128) s4[i] = w4[i];
    }

    const int lane = t & 31, w = t >> 5;
    const int ct = lane & 3;          // col group: cols 8*ct..8*ct+7
    const int rbase = w * 64 + (lane >> 2);   // + 8*r, r = 0..7

    unsigned long long acc[8][4];
    #pragma unroll
    for (int r = 0; r < 8; r++)
        #pragma unroll
        for (int c = 0; c < 4; c++) acc[r][c] = 0ull;

    for (int ch = 0; ch < 4; ch++) {
        __syncthreads();   // previous-chunk consumers done (also orders W store)
        {   // stage x rows row0..row0+255, k = ch*32..ch*32+31 (8 f4/row)
            const float4* xg = (const float4*)x;
            #pragma unroll
            for (int i = t; i < 2048; i += 128) {
                int r = i >> 3, c = i & 7;
                float4 v = make_float4(0.f, 0.f, 0.f, 0.f);
                int row = row0 + r;
                if (row < n) v = xg[(size_t)row * 32 + ch * 8 + c];
                *(float4*)&xs[r * 36 + c * 4] = v;
            }
        }
        __syncthreads();

        #pragma unroll
        for (int k4 = 0; k4 < 8; k4++) {
            float4 xv[8];
            #pragma unroll
            for (int r = 0; r < 8; r++)
                xv[r] = *(const float4*)&xs[(rbase + 8 * r) * 36 + k4 * 4];
            #pragma unroll
            for (int u = 0; u < 4; u++) {
                int k = ch * 32 + k4 * 4 + u;
                const ulonglong2* wp = (const ulonglong2*)&ws[k * H1 + ct * 8];
                ulonglong2 wA = wp[0];
                ulonglong2 wB = wp[1];
                #pragma unroll
                for (int r = 0; r < 8; r++) {
                    float xsc = (u == 0) ? xv[r].x : (u == 1) ? xv[r].y
                              : (u == 2) ? xv[r].z : xv[r].w;
                    unsigned long long xx = pack_dup(xsc);
                    ffma2(acc[r][0], xx, wA.x);
                    ffma2(acc[r][1], xx, wA.y);
                    ffma2(acc[r][2], xx, wB.x);
                    ffma2(acc[r][3], xx, wB.y);
                }
            }
        }
    }

    #pragma unroll
    for (int r = 0; r < 8; r++) {
        int row = row0 + rbase + 8 * r;
        if (row < n) {
            float dv = rsqrtf((float)(g_cnt[row] + 1));   // +1 self loop
            if (ct == 0) g_dinv[row] = dv;
            F2U a0, a1, a2, a3;
            a0.u = acc[r][0]; a1.u = acc[r][1]; a2.u = acc[r][2]; a3.u = acc[r][3];
            float4* A4 = (float4*)(g_A + (size_t)row * H1) + ct * 2;
            A4[0] = make_float4(a0.f.x * dv, a0.f.y * dv, a1.f.x * dv, a1.f.y * dv);
            A4[1] = make_float4(a2.f.x * dv, a2.f.y * dv, a3.f.x * dv, a3.f.y * dv);
        }
    }
}

// ---------------- layer1 fused: gather1 + relu + GEMM2 ----------------------
// Warp per node. Edge rows (128B) loaded 4-edges-per-warp-LDG:
//   lane l: g = l>>3 selects edge within quad, sub = l&7 selects 16B chunk.
// Then h1 kept in per-warp smem; y2 = (h1@W2)*dinv computed warp-locally.

__global__ void k_layer1(const float* __restrict__ b1, const float* __restrict__ W2, int n) {
    __shared__ float w2s[H1 * 17];          // padded: W2[k][j] at k*17+j
    __shared__ float h1s[8][H1];            // per-warp h1 buffer
    const int t = threadIdx.x;
    for (int i = t; i < H1 * H2; i += 256) {
        w2s[(i >> 4) * 17 + (i & 15)] = W2[i];
    }
    __syncthreads();

    int wid = t >> 5;
    int node = blockIdx.x * 8 + wid;
    if (node >= n) return;
    int lane = t & 31;
    int g = lane >> 3;       // 0..3  edge-in-quad
    int sub = lane & 7;      // 0..7  16B chunk of the 128B row

    int beg = g_rowstart[node], end = g_rowstart[node + 1];
    float4 acc = make_float4(0.f, 0.f, 0.f, 0.f);

    int j = beg & ~3;
    // 2 quads per iteration for MLP
    for (; j + 4 < end; j += 8) {
        int i0 = j + g;
        int i1 = j + 4 + g;
        int s0 = g_eidx[i0];
        int s1 = (i1 < EE) ? g_eidx[i1] : 0;
        bool a0 = (i0 >= beg) & (i0 < end);
        bool a1 = (i1 >= beg) & (i1 < end);
        if (a0) {
            float4 v = *(const float4*)&g_A[(size_t)s0 * H1 + sub * 4];
            acc.x += v.x; acc.y += v.y; acc.z += v.z; acc.w += v.w;
        }
        if (a1) {
            float4 v = *(const float4*)&g_A[(size_t)s1 * H1 + sub * 4];
            acc.x += v.x; acc.y += v.y; acc.z += v.z; acc.w += v.w;
        }
    }
    if (j < end) {           // last quad
        int i0 = j + g;
        int s0 = g_eidx[i0];
        if (i0 >= beg && i0 < end) {
            float4 v = *(const float4*)&g_A[(size_t)s0 * H1 + sub * 4];
            acc.x += v.x; acc.y += v.y; acc.z += v.z; acc.w += v.w;
        }
    }

    // reduce over the 4 edge groups (lanes differing in bits 3,4)
    #pragma unroll
    for (int off = 8; off <= 16; off <<= 1) {
        acc.x += __shfl_xor_sync(0xffffffffu, acc.x, off);
        acc.y += __shfl_xor_sync(0xffffffffu, acc.y, off);
        acc.z += __shfl_xor_sync(0xffffffffu, acc.z, off);
        acc.w += __shfl_xor_sync(0xffffffffu, acc.w, off);
    }

    // self loop + norm + bias + relu
    float dv = g_dinv[node];
    float4 self = *(const float4*)&g_A[(size_t)node * H1 + sub * 4];
    float4 bb = *(const float4*)&b1[sub * 4];
    float4 h;
    h.x = fmaxf((acc.x + self.x) * dv + bb.x, 0.f);
    h.y = fmaxf((acc.y + self.y) * dv + bb.y, 0.f);
    h.z = fmaxf((acc.z + self.z) * dv + bb.z, 0.f);
    h.w = fmaxf((acc.w + self.w) * dv + bb.w, 0.f);

    if (g == 0) *(float4*)&h1s[wid][sub * 4] = h;
    __syncwarp();

    // GEMM2: y2[jj] = dinv * sum_k h1[k] * W2[k][jj]
    int half = lane >> 4;    // 0/1: k range
    int jj = lane & 15;
    float acc2 = 0.f;
    #pragma unroll
    for (int i = 0; i < 16; i++) {
        int k = half * 16 + i;
        acc2 += h1s[wid][k] * w2s[k * 17 + jj];
    }
    acc2 += __shfl_xor_sync(0xffffffffu, acc2, 16);
    if (half == 0) g_C[(size_t)node * H2 + jj] = acc2 * dv;
}

// ---------------- layer2 fused: gather2 + relu + FC + log_softmax -----------
// Warp per node. Edge rows (64B) loaded 8-edges-per-warp-LDG:
//   lane l: g = l>>2 edge-in-octet, sub = l&3 16B chunk of the 64B row.

__global__ void k_layer2(const float* __restrict__ b2,
                         const float* __restrict__ Wfc,
                         const float* __restrict__ bfc,
                         float* __restrict__ out, int n) {
    int t = threadIdx.x;
    int wid = t >> 5;
    int node = blockIdx.x * 8 + wid;
    if (node >= n) return;
    int lane = t & 31;
    int g = lane >> 2;       // 0..7
    int sub = lane & 3;      // 0..3

    int beg = g_rowstart[node], end = g_rowstart[node + 1];
    float4 acc = make_float4(0.f, 0.f, 0.f, 0.f);

    int j = beg & ~7;
    for (; j + 8 < end; j += 16) {
        int i0 = j + g;
        int i1 = j + 8 + g;
        int s0 = g_eidx[i0];
        int s1 = (i1 < EE) ? g_eidx[i1] : 0;
        if (i0 >= beg && i0 < end) {
            float4 v = *(const float4*)&g_C[(size_t)s0 * H2 + sub * 4];
            acc.x += v.x; acc.y += v.y; acc.z += v.z; acc.w += v.w;
        }
        if (i1 >= beg && i1 < end) {
            float4 v = *(const float4*)&g_C[(size_t)s1 * H2 + sub * 4];
            acc.x += v.x; acc.y += v.y; acc.z += v.z; acc.w += v.w;
        }
    }
    if (j < end) {
        int i0 = j + g;
        int s0 = g_eidx[i0];
        if (i0 >= beg && i0 < end) {
            float4 v = *(const float4*)&g_C[(size_t)s0 * H2 + sub * 4];
            acc.x += v.x; acc.y += v.y; acc.z += v.z; acc.w += v.w;
        }
    }

    // reduce over the 8 edge groups (lanes differing in bits 2,3,4)
    #pragma unroll
    for (int off = 4; off <= 16; off <<= 1) {
        acc.x += __shfl_xor_sync(0xffffffffu, acc.x, off);
        acc.y += __shfl_xor_sync(0xffffffffu, acc.y, off);
        acc.z += __shfl_xor_sync(0xffffffffu, acc.z, off);
        acc.w += __shfl_xor_sync(0xffffffffu, acc.w, off);
    }

    float dv = g_dinv[node];
    float4 self = *(const float4*)&g_C[(size_t)node * H2 + sub * 4];
    float4 bb = *(const float4*)&b2[sub * 4];
    float4 h;
    h.x = fmaxf((acc.x + self.x) * dv + bb.x, 0.f);
    h.y = fmaxf((acc.y + self.y) * dv + bb.y, 0.f);
    h.z = fmaxf((acc.z + self.z) * dv + bb.z, 0.f);
    h.w = fmaxf((acc.w + self.w) * dv + bb.w, 0.f);

    // FC: Wfc row-major [16,2]; lane covers channels sub*4..sub*4+3
    const float4* wf = (const float4*)Wfc;
    float4 f0 = wf[sub * 2];       // {W[4s][0],W[4s][1],W[4s+1][0],W[4s+1][1]}
    float4 f1 = wf[sub * 2 + 1];
    float p0 = h.x * f0.x + h.y * f0.z + h.z * f1.x + h.w * f1.z;
    float p1 = h.x * f0.y + h.y * f0.w + h.z * f1.y + h.w * f1.w;
    p0 += __shfl_xor_sync(0xffffffffu, p0, 1);
    p1 += __shfl_xor_sync(0xffffffffu, p1, 1);
    p0 += __shfl_xor_sync(0xffffffffu, p0, 2);
    p1 += __shfl_xor_sync(0xffffffffu, p1, 2);

    if (lane == 0) {
        float l0 = p0 + bfc[0];
        float l1 = p1 + bfc[1];
        float m = fmaxf(l0, l1);
        float lse = m + logf(expf(l0 - m) + expf(l1 - m));
        ((float2*)out)[node] = make_float2(l0 - lse, l1 - lse);
    }
}

// ---------------- launch -----------------------------------------------------

extern "C" void kernel_launch(void* const* d_in, const int* in_sizes, int n_in,
                              void* d_out, int out_size) {
    const float* x   = (const float*)d_in[0];
    const int*   ei  = (const int*)d_in[1];     // int32 (JAX default x64 off)
    const float* W1  = (const float*)d_in[2];
    const float* b1  = (const float*)d_in[3];
    const float* W2  = (const float*)d_in[4];
    const float* b2  = (const float*)d_in[5];
    const float* Wfc = (const float*)d_in[6];
    const float* bfc = (const float*)d_in[7];
    float* out = (float*)d_out;

    const int n = in_sizes[0] / IN_DIM;   // 500000
    const int e = in_sizes[1] / 2;        // 8000000 (divisible by 8)
    const int nb = (n + SCAN_BLK - 1) / SCAN_BLK;
    const int T = 256;

    k_init<<<(n / 4 + T - 1) / T, T>>>(n / 4);
    k_hist<<<(e / 4 + T - 1) / T, T>>>(ei, e);

    if (g_ctx.ok) {
        // Fork: scan/fill chain on s1, gemm1 on the main stream — disjoint
        // pipes (L2-atomic vs FMA/L1), overlap hides the shorter chain.
        cudaEventRecord(g_ctx.e1, 0);
        cudaStreamWaitEvent(g_ctx.s1, g_ctx.e1, 0);
        k_scan_a<<<nb, SCAN_BLK, 0, g_ctx.s1>>>(n);
        k_scan_b<<<1, SCAN_BLK, 0, g_ctx.s1>>>(nb);
        k_scan_c<<<(n + T - 1) / T, T, 0, g_ctx.s1>>>(n, e);
        k_fill<<<(e / 4 + T - 1) / T, T, 0, g_ctx.s1>>>(ei, e);
        cudaEventRecord(g_ctx.e2, g_ctx.s1);

        k_gemm1<<<(n + 255) / 256, 128>>>(x, W1, n);

        cudaStreamWaitEvent(0, g_ctx.e2, 0);   // join before layer1
    } else {
        k_scan_a<<<nb, SCAN_BLK>>>(n);
        k_scan_b<<<1, SCAN_BLK>>>(nb);
        k_scan_c<<<(n + T - 1) / T, T>>>(n, e);
        k_fill<<<(e / 4 + T - 1) / T, T>>>(ei, e);
        k_gemm1<<<(n + 255) / 256, 128>>>(x, W1, n);
    }

    k_layer1<<<(n + 7) / 8, 256>>>(b1, W2, n);
    k_layer2<<<(n + 7) / 8, 256>>>(b2, Wfc, bfc, out, n);
}

// round 15
// speedup vs baseline: 1.1258x; 1.1258x over previous
#include <cuda_runtime.h>
#include <cuda_bf16.h>
#include <math.h>

// Problem constants (fixed by the dataset)
#define NN 500000
#define EE 8000000
#define IN_DIM 128
#define H1 32
#define H2 16
#define SCAN_BLK 1024
#define NB_SCAN ((NN + SCAN_BLK - 1) / SCAN_BLK)   // 489

// Scratch (device globals; no cudaMalloc allowed)
__device__ float g_A[NN * H1];        // y1 = (x@W1)*dinv
__device__ float g_C[NN * H2];        // y2 = (h1@W2)*dinv
__device__ int   g_eidx[EE];          // CSR: src ids grouped by dst
__device__ int   g_cnt[NN];           // edge in-degree (no self loop)
__device__ int   g_cur[NN];           // fill cursors (primed to rowstart)
__device__ int   g_scan[NN];          // per-block inclusive scan of cnt
__device__ int   g_bsum[NB_SCAN];     // block totals
__device__ int   g_boff[NB_SCAN];     // exclusive scan of block totals
__device__ int   g_rowstart[NN + 1];
__device__ float g_dinv[NN];

// ---------------- packed f32x2 helpers --------------------------------------

union F2U { unsigned long long u; float2 f; };

__device__ __forceinline__ unsigned long long pack_dup(float x) {
    unsigned long long r;
    asm("mov.b64 %0, {%1, %1};" : "=l"(r) : "f"(x));
    return r;
}
__device__ __forceinline__ void ffma2(unsigned long long& acc,
                                      unsigned long long a, unsigned long long b) {
    asm("fma.rn.f32x2 %0, %1, %2, %0;" : "+l"(acc) : "l"(a), "l"(b));
}

// ---------------- init / histogram / CSR fill -------------------------------

__global__ void k_init(int n4) {   // n4 = NN/4, zero cnt only
    int i = blockIdx.x * blockDim.x + threadIdx.x;
    if (i < n4) ((int4*)g_cnt)[i] = make_int4(0, 0, 0, 0);
}

__global__ void k_hist(const int* __restrict__ ei, int e) {
    int i = blockIdx.x * blockDim.x + threadIdx.x;   // over e/4
    if (i >= (e >> 2)) return;
    int4 d = ((const int4*)(ei + e))[i];
    atomicAdd(&g_cnt[d.x], 1);
    atomicAdd(&g_cnt[d.y], 1);
    atomicAdd(&g_cnt[d.z], 1);
    atomicAdd(&g_cnt[d.w], 1);
}

// ---------------- two-level exclusive scan of g_cnt -> g_rowstart -----------

__global__ void k_scan_a(int n) {
    __shared__ int s[SCAN_BLK];
    int t = threadIdx.x;
    int i = blockIdx.x * SCAN_BLK + t;
    int v = (i < n) ? g_cnt[i] : 0;
    s[t] = v;
    __syncthreads();
    #pragma unroll
    for (int off = 1; off < SCAN_BLK; off <<= 1) {
        int tv = (t >= off) ? s[t - off] : 0;
        __syncthreads();
        s[t] += tv;
        __syncthreads();
    }
    if (i < n) g_scan[i] = s[t];
    if (t == SCAN_BLK - 1) g_bsum[blockIdx.x] = s[t];
}

__global__ void k_scan_b(int nb) {
    __shared__ int s[SCAN_BLK];
    int t = threadIdx.x;
    int v = (t < nb) ? g_bsum[t] : 0;
    s[t] = v;
    __syncthreads();
    #pragma unroll
    for (int off = 1; off < SCAN_BLK; off <<= 1) {
        int tv = (t >= off) ? s[t - off] : 0;
        __syncthreads();
        s[t] += tv;
        __syncthreads();
    }
    if (t < nb) g_boff[t] = s[t] - v;   // exclusive
}

// writes rowstart AND primes the fill cursors with it
__global__ void k_scan_c(int n, int e) {
    int i = blockIdx.x * blockDim.x + threadIdx.x;
    if (i < n) {
        int rs = g_scan[i] - g_cnt[i] + g_boff[i / SCAN_BLK];  // exclusive
        g_rowstart[i] = rs;
        g_cur[i] = rs;
    }
    if (i == 0) g_rowstart[n] = e;
}

// cursor-primed fill: atomicAdd's return IS the slot (no rowstart load)
__global__ void k_fill(const int* __restrict__ ei, int e) {
    int i = blockIdx.x * blockDim.x + threadIdx.x;   // over e/4
    if (i >= (e >> 2)) return;
    int4 s = ((const int4*)ei)[i];
    int4 d = ((const int4*)(ei + e))[i];
    int p0 = atomicAdd(&g_cur[d.x], 1);
    int p1 = atomicAdd(&g_cur[d.y], 1);
    int p2 = atomicAdd(&g_cur[d.z], 1);
    int p3 = atomicAdd(&g_cur[d.w], 1);
    g_eidx[p0] = s.x;
    g_eidx[p1] = s.y;
    g_eidx[p2] = s.z;
    g_eidx[p3] = s.w;
}

// ---------------- GEMM1: g_A = (x @ W1) * dinv[row]; also stores dinv -------
// Register-blocked 8x8: block = 128 threads covering 256 rows x 32 cols.
// Per warp-k: 8 wf (W) + 8 wf (x) for 32 FFMA2.

__global__ void __launch_bounds__(128, 4)
k_gemm1(const float* __restrict__ x, const float* __restrict__ W1, int n) {
    __shared__ __align__(16) float ws[IN_DIM * H1];   // 16 KB
    __shared__ __align__(16) float xs[256 * 36];      // 36 KB
    const int t = threadIdx.x;
    const int row0 = blockIdx.x * 256;

    {   // W1: 128x32 = 1024 float4
        const float4* w4 = (const float4*)W1;
        float4* s4 = (float4*)ws;
        #pragma unroll
        for (int i = t; i < 1024; i += 128) s4[i] = w4[i];
    }

    const int lane = t & 31, w = t >> 5;
    const int ct = lane & 3;          // col group: cols 8*ct..8*ct+7
    const int rbase = w * 64 + (lane >> 2);   // + 8*r, r = 0..7

    unsigned long long acc[8][4];
    #pragma unroll
    for (int r = 0; r < 8; r++)
        #pragma unroll
        for (int c = 0; c < 4; c++) acc[r][c] = 0ull;

    for (int ch = 0; ch < 4; ch++) {
        __syncthreads();   // previous-chunk consumers done (also orders W store)
        {   // stage x rows row0..row0+255, k = ch*32..ch*32+31 (8 f4/row)
            const float4* xg = (const float4*)x;
            #pragma unroll
            for (int i = t; i < 2048; i += 128) {
                int r = i >> 3, c = i & 7;
                float4 v = make_float4(0.f, 0.f, 0.f, 0.f);
                int row = row0 + r;
                if (row < n) v = xg[(size_t)row * 32 + ch * 8 + c];
                *(float4*)&xs[r * 36 + c * 4] = v;
            }
        }
        __syncthreads();

        #pragma unroll
        for (int k4 = 0; k4 < 8; k4++) {
            float4 xv[8];
            #pragma unroll
            for (int r = 0; r < 8; r++)
                xv[r] = *(const float4*)&xs[(rbase + 8 * r) * 36 + k4 * 4];
            #pragma unroll
            for (int u = 0; u < 4; u++) {
                int k = ch * 32 + k4 * 4 + u;
                const ulonglong2* wp = (const ulonglong2*)&ws[k * H1 + ct * 8];
                ulonglong2 wA = wp[0];
                ulonglong2 wB = wp[1];
                #pragma unroll
                for (int r = 0; r < 8; r++) {
                    float xsc = (u == 0) ? xv[r].x : (u == 1) ? xv[r].y
                              : (u == 2) ? xv[r].z : xv[r].w;
                    unsigned long long xx = pack_dup(xsc);
                    ffma2(acc[r][0], xx, wA.x);
                    ffma2(acc[r][1], xx, wA.y);
                    ffma2(acc[r][2], xx, wB.x);
                    ffma2(acc[r][3], xx, wB.y);
                }
            }
        }
    }

    #pragma unroll
    for (int r = 0; r < 8; r++) {
        int row = row0 + rbase + 8 * r;
        if (row < n) {
            float dv = rsqrtf((float)(g_cnt[row] + 1));   // +1 self loop
            if (ct == 0) g_dinv[row] = dv;
            F2U a0, a1, a2, a3;
            a0.u = acc[r][0]; a1.u = acc[r][1]; a2.u = acc[r][2]; a3.u = acc[r][3];
            float4* A4 = (float4*)(g_A + (size_t)row * H1) + ct * 2;
            A4[0] = make_float4(a0.f.x * dv, a0.f.y * dv, a1.f.x * dv, a1.f.y * dv);
            A4[1] = make_float4(a2.f.x * dv, a2.f.y * dv, a3.f.x * dv, a3.f.y * dv);
        }
    }
}

// ---------------- layer1 fused: gather1 + relu + GEMM2 ----------------------
// Warp per node. Edge rows (128B) loaded 4-edges-per-warp-LDG:
//   lane l: g = l>>3 edge-in-quad, sub = l&7 16B chunk of the 128B row.
// Main loop guard-free (starts at beg, 8 edges/iter); tail handles <8.

__global__ void k_layer1(const float* __restrict__ b1, const float* __restrict__ W2, int n) {
    __shared__ float w2s[H1 * 17];          // padded: W2[k][j] at k*17+j
    __shared__ float h1s[8][H1];            // per-warp h1 buffer
    const int t = threadIdx.x;
    for (int i = t; i < H1 * H2; i += 256) {
        w2s[(i >> 4) * 17 + (i & 15)] = W2[i];
    }
    __syncthreads();

    int wid = t >> 5;
    int node = blockIdx.x * 8 + wid;
    if (node >= n) return;
    int lane = t & 31;
    int g = lane >> 3;       // 0..3  edge-in-quad
    int sub = lane & 7;      // 0..7  16B chunk of the 128B row

    int beg = g_rowstart[node], end = g_rowstart[node + 1];
    float4 acc = make_float4(0.f, 0.f, 0.f, 0.f);

    int j = beg;
    for (; j + 8 <= end; j += 8) {         // unguarded: all 8 edges valid
        int s0 = g_eidx[j + g];
        int s1 = g_eidx[j + 4 + g];
        float4 v0 = *(const float4*)&g_A[(size_t)s0 * H1 + sub * 4];
        float4 v1 = *(const float4*)&g_A[(size_t)s1 * H1 + sub * 4];
        acc.x += v0.x + v1.x;
        acc.y += v0.y + v1.y;
        acc.z += v0.z + v1.z;
        acc.w += v0.w + v1.w;
    }
    {   // tail: <8 edges, two guarded quads
        int i0 = j + g;
        int i1 = j + 4 + g;
        if (i0 < end) {
            float4 v = *(const float4*)&g_A[(size_t)g_eidx[i0] * H1 + sub * 4];
            acc.x += v.x; acc.y += v.y; acc.z += v.z; acc.w += v.w;
        }
        if (i1 < end) {
            float4 v = *(const float4*)&g_A[(size_t)g_eidx[i1] * H1 + sub * 4];
            acc.x += v.x; acc.y += v.y; acc.z += v.z; acc.w += v.w;
        }
    }

    // reduce over the 4 edge groups (lanes differing in bits 3,4)
    #pragma unroll
    for (int off = 8; off <= 16; off <<= 1) {
        acc.x += __shfl_xor_sync(0xffffffffu, acc.x, off);
        acc.y += __shfl_xor_sync(0xffffffffu, acc.y, off);
        acc.z += __shfl_xor_sync(0xffffffffu, acc.z, off);
        acc.w += __shfl_xor_sync(0xffffffffu, acc.w, off);
    }

    // self loop + norm + bias + relu
    float dv = g_dinv[node];
    float4 self = *(const float4*)&g_A[(size_t)node * H1 + sub * 4];
    float4 bb = *(const float4*)&b1[sub * 4];
    float4 h;
    h.x = fmaxf((acc.x + self.x) * dv + bb.x, 0.f);
    h.y = fmaxf((acc.y + self.y) * dv + bb.y, 0.f);
    h.z = fmaxf((acc.z + self.z) * dv + bb.z, 0.f);
    h.w = fmaxf((acc.w + self.w) * dv + bb.w, 0.f);

    if (g == 0) *(float4*)&h1s[wid][sub * 4] = h;
    __syncwarp();

    // GEMM2: y2[jj] = dinv * sum_k h1[k] * W2[k][jj]
    int half = lane >> 4;    // 0/1: k range
    int jj = lane & 15;
    float acc2 = 0.f;
    #pragma unroll
    for (int i = 0; i < 16; i++) {
        int k = half * 16 + i;
        acc2 += h1s[wid][k] * w2s[k * 17 + jj];
    }
    acc2 += __shfl_xor_sync(0xffffffffu, acc2, 16);
    if (half == 0) g_C[(size_t)node * H2 + jj] = acc2 * dv;
}

// ---------------- layer2 fused: gather2 + relu + FC + log_softmax -----------
// Warp per node. Edge rows (64B) loaded 8-edges-per-warp-LDG:
//   lane l: g = l>>2 edge-in-octet, sub = l&3 16B chunk of the 64B row.
// Main loop guard-free (16 edges/iter); tail handles <16.

__global__ void k_layer2(const float* __restrict__ b2,
                         const float* __restrict__ Wfc,
                         const float* __restrict__ bfc,
                         float* __restrict__ out, int n) {
    int t = threadIdx.x;
    int wid = t >> 5;
    int node = blockIdx.x * 8 + wid;
    if (node >= n) return;
    int lane = t & 31;
    int g = lane >> 2;       // 0..7
    int sub = lane & 3;      // 0..3

    int beg = g_rowstart[node], end = g_rowstart[node + 1];
    float4 acc = make_float4(0.f, 0.f, 0.f, 0.f);

    int j = beg;
    for (; j + 16 <= end; j += 16) {       // unguarded: all 16 edges valid
        int s0 = g_eidx[j + g];
        int s1 = g_eidx[j + 8 + g];
        float4 v0 = *(const float4*)&g_C[(size_t)s0 * H2 + sub * 4];
        float4 v1 = *(const float4*)&g_C[(size_t)s1 * H2 + sub * 4];
        acc.x += v0.x + v1.x;
        acc.y += v0.y + v1.y;
        acc.z += v0.z + v1.z;
        acc.w += v0.w + v1.w;
    }
    {   // tail: <16 edges, two guarded octets
        int i0 = j + g;
        int i1 = j + 8 + g;
        if (i0 < end) {
            float4 v = *(const float4*)&g_C[(size_t)g_eidx[i0] * H2 + sub * 4];
            acc.x += v.x; acc.y += v.y; acc.z += v.z; acc.w += v.w;
        }
        if (i1 < end) {
            float4 v = *(const float4*)&g_C[(size_t)g_eidx[i1] * H2 + sub * 4];
            acc.x += v.x; acc.y += v.y; acc.z += v.z; acc.w += v.w;
        }
    }

    // reduce over the 8 edge groups (lanes differing in bits 2,3,4)
    #pragma unroll
    for (int off = 4; off <= 16; off <<= 1) {
        acc.x += __shfl_xor_sync(0xffffffffu, acc.x, off);
        acc.y += __shfl_xor_sync(0xffffffffu, acc.y, off);
        acc.z += __shfl_xor_sync(0xffffffffu, acc.z, off);
        acc.w += __shfl_xor_sync(0xffffffffu, acc.w, off);
    }

    float dv = g_dinv[node];
    float4 self = *(const float4*)&g_C[(size_t)node * H2 + sub * 4];
    float4 bb = *(const float4*)&b2[sub * 4];
    float4 h;
    h.x = fmaxf((acc.x + self.x) * dv + bb.x, 0.f);
    h.y = fmaxf((acc.y + self.y) * dv + bb.y, 0.f);
    h.z = fmaxf((acc.z + self.z) * dv + bb.z, 0.f);
    h.w = fmaxf((acc.w + self.w) * dv + bb.w, 0.f);

    // FC: Wfc row-major [16,2]; lane covers channels sub*4..sub*4+3
    const float4* wf = (const float4*)Wfc;
    float4 f0 = wf[sub * 2];       // {W[4s][0],W[4s][1],W[4s+1][0],W[4s+1][1]}
    float4 f1 = wf[sub * 2 + 1];
    float p0 = h.x * f0.x + h.y * f0.z + h.z * f1.x + h.w * f1.z;
    float p1 = h.x * f0.y + h.y * f0.w + h.z * f1.y + h.w * f1.w;
    p0 += __shfl_xor_sync(0xffffffffu, p0, 1);
    p1 += __shfl_xor_sync(0xffffffffu, p1, 1);
    p0 += __shfl_xor_sync(0xffffffffu, p0, 2);
    p1 += __shfl_xor_sync(0xffffffffu, p1, 2);

    if (lane == 0) {
        float l0 = p0 + bfc[0];
        float l1 = p1 + bfc[1];
        float m = fmaxf(l0, l1);
        float lse = m + logf(expf(l0 - m) + expf(l1 - m));
        ((float2*)out)[node] = make_float2(l0 - lse, l1 - lse);
    }
}

// ---------------- launch -----------------------------------------------------

extern "C" void kernel_launch(void* const* d_in, const int* in_sizes, int n_in,
                              void* d_out, int out_size) {
    const float* x   = (const float*)d_in[0];
    const int*   ei  = (const int*)d_in[1];     // int32 (JAX default x64 off)
    const float* W1  = (const float*)d_in[2];
    const float* b1  = (const float*)d_in[3];
    const float* W2  = (const float*)d_in[4];
    const float* b2  = (const float*)d_in[5];
    const float* Wfc = (const float*)d_in[6];
    const float* bfc = (const float*)d_in[7];
    float* out = (float*)d_out;

    const int n = in_sizes[0] / IN_DIM;   // 500000
    const int e = in_sizes[1] / 2;        // 8000000 (divisible by 8)
    const int nb = (n + SCAN_BLK - 1) / SCAN_BLK;
    const int T = 256;

    // Sequential, CSR build first (streams overlap regressed in R13: the
    // fill chain and gemm1 contend for L2, not disjoint pipes).
    k_init<<<(n / 4 + T - 1) / T, T>>>(n / 4);
    k_hist<<<(e / 4 + T - 1) / T, T>>>(ei, e);
    k_scan_a<<<nb, SCAN_BLK>>>(n);
    k_scan_b<<<1, SCAN_BLK>>>(nb);
    k_scan_c<<<(n + T - 1) / T, T>>>(n, e);
    k_fill<<<(e / 4 + T - 1) / T, T>>>(ei, e);
    k_gemm1<<<(n + 255) / 256, 128>>>(x, W1, n);
    k_layer1<<<(n + 7) / 8, 256>>>(b1, W2, n);
    k_layer2<<<(n + 7) / 8, 256>>>(b2, Wfc, bfc, out, n);
}